// round 15
// baseline (speedup 1.0000x reference)
#include <cuda_runtime.h>

// ============================================================================
// AdditiveAttention: out = softmax_k( sum_h w_v[h]*tanh(qW_q + kW_k) ) @ V
// B=16, NQ=64, NK=512, QS=KS=H=VD=256, fp32.
//
// R15 = R14 (tf32 proj + split-K partial softmax) with the MUFU eliminated
// from the score inner loop via  e^{2(q+k)} = e^{2q} * e^{2k}:
//   proj epilogue stores eq = 2^(C2*q), ek = 2^(C2*k)   (C2 = 2*log2 e)
//   score elem: tanh = 1 - 2*rcp(1 + eq*ek); rcp = bit-seed + 2 Newton (FMA).
// Packed f32x2 FFMA2 (PTX fma.rn.f32x2) -> ~7 cyc/elem on fma pipe vs
// ~26-29 cyc on the measured-slow MUFU path. Calibration: TANH ~29,
// EX2/RCP ~17 cyc/warp-op (R8/R11/R12).
// ============================================================================

// scratch (allocation-free rule -> __device__ globals; zero-initialized)
__device__ float g_qh[16 * 64 * 256];        // 4 MB: 2^(C2 * queries@W_q)
__device__ float g_kh[16 * 512 * 256];       // 8 MB: 2^(C2 * keys@W_k)
__device__ float g_po[512 * 8 * 256];        // 4 MB: partial outputs
__device__ float g_pm[512 * 8];              // partial maxes
__device__ float g_ps[512 * 8];              // partial sums

#define L2E     1.4426950408889634f
#define C2SCALE 2.885390081777927f           // 2*log2(e)

typedef unsigned long long u64;
#define ONE2  0x3F8000003F800000ULL          // {1.0f, 1.0f}
#define TWO2  0x4000000040000000ULL          // {2.0f, 2.0f}

__device__ __forceinline__ float ex2_fast(float x) {
    float r; asm("ex2.approx.f32 %0, %1;" : "=f"(r) : "f"(x)); return r;
}
__device__ __forceinline__ float rcp_fast(float x) {
    float r; asm("rcp.approx.f32 %0, %1;" : "=f"(r) : "f"(x)); return r;
}
__device__ __forceinline__ unsigned f2tf32(float x) {
    unsigned u; asm("cvt.rna.tf32.f32 %0, %1;" : "=r"(u) : "f"(x)); return u;
}
__device__ __forceinline__ u64 fma2(u64 a, u64 b, u64 c) {
    u64 d; asm("fma.rn.f32x2 %0, %1, %2, %3;" : "=l"(d) : "l"(a), "l"(b), "l"(c));
    return d;
}
__device__ __forceinline__ u64 mul2(u64 a, u64 b) {
    u64 d; asm("mul.rn.f32x2 %0, %1, %2;" : "=l"(d) : "l"(a), "l"(b));
    return d;
}
// packed reciprocal of x (both halves >= 1): magic seed + 2 Newton, rel ~1e-5
__device__ __forceinline__ u64 rcp2_nr(u64 x, u64 nx) {
    unsigned rl = 0x7EF311C3u - (unsigned)x;
    unsigned rh = 0x7EF311C3u - (unsigned)(x >> 32);
    u64 r = (u64)rl | ((u64)rh << 32);
    r = mul2(r, fma2(nx, r, TWO2));
    r = mul2(r, fma2(nx, r, TWO2));
    return r;
}
__device__ __forceinline__ void cp_async16(void* smem_dst, const void* gmem_src) {
    unsigned s = (unsigned)__cvta_generic_to_shared(smem_dst);
    asm volatile("cp.async.cg.shared.global [%0], [%1], 16;\n" :: "r"(s), "l"(gmem_src));
}
__device__ __forceinline__ void cp_async_commit() {
    asm volatile("cp.async.commit_group;\n" ::);
}
__device__ __forceinline__ void cp_async_wait1() {
    asm volatile("cp.async.wait_group 1;\n" ::);
}
__device__ __forceinline__ void cp_async_wait0() {
    asm volatile("cp.async.wait_group 0;\n" ::);
}

// ----------------------------------------------------------------------------
// tf32 tensor-core projection GEMM (R14), epilogue stores 2^(C2*acc).
// ----------------------------------------------------------------------------
#define AS_S 20
#define BS_S 140

__global__ __launch_bounds__(256, 2)
void proj_tf32_kernel(const float* __restrict__ queries,
                      const float* __restrict__ keys,
                      const float* __restrict__ Wq,
                      const float* __restrict__ Wk,
                      const int* __restrict__ valid_lens,
                      float* __restrict__ qh,
                      float* __restrict__ kh) {
    __shared__ unsigned As[64 * AS_S];
    __shared__ unsigned Bs[16 * BS_S];

    const int tid    = threadIdx.x;
    const int warp   = tid >> 5;
    const int lane   = tid & 31;
    const int g      = lane >> 2;
    const int t      = lane & 3;
    const int warp_m = warp & 1;
    const int warp_n = warp >> 1;
    const int bm     = blockIdx.y * 64;
    const int bn     = blockIdx.x * 128;

    const float* A; const float* W; float* C; int rowbase;
    if (bm < 1024) { A = queries; W = Wq; C = qh; rowbase = bm; }
    else {
        A = keys; W = Wk; C = kh; rowbase = bm - 1024;
        if ((rowbase & 511) >= valid_lens[rowbase >> 9]) return;
    }

    const int arow = tid >> 2;
    const int acol = (tid & 3) * 4;
    const int brow = tid >> 4;
    const int bcol = (tid & 15) * 4;

    float acc[2][4][4] = {};

    float4 av  = *(const float4*)&A[(rowbase + arow) * 256 + acol];
    float4 bv0 = *(const float4*)&W[brow * 256 + bn + bcol];
    float4 bv1 = *(const float4*)&W[brow * 256 + bn + bcol + 64];

    for (int k0 = 0; k0 < 256; k0 += 16) {
        {
            uint4 ua = make_uint4(f2tf32(av.x), f2tf32(av.y),
                                  f2tf32(av.z), f2tf32(av.w));
            *(uint4*)&As[arow * AS_S + acol] = ua;
            uint4 ub0 = make_uint4(f2tf32(bv0.x), f2tf32(bv0.y),
                                   f2tf32(bv0.z), f2tf32(bv0.w));
            uint4 ub1 = make_uint4(f2tf32(bv1.x), f2tf32(bv1.y),
                                   f2tf32(bv1.z), f2tf32(bv1.w));
            *(uint4*)&Bs[brow * BS_S + bcol]      = ub0;
            *(uint4*)&Bs[brow * BS_S + bcol + 64] = ub1;
        }
        __syncthreads();

        if (k0 + 16 < 256) {
            av  = *(const float4*)&A[(rowbase + arow) * 256 + k0 + 16 + acol];
            bv0 = *(const float4*)&W[(k0 + 16 + brow) * 256 + bn + bcol];
            bv1 = *(const float4*)&W[(k0 + 16 + brow) * 256 + bn + bcol + 64];
        }

        #pragma unroll
        for (int ks = 0; ks < 16; ks += 8) {
            unsigned a[2][4], b[4][2];
            #pragma unroll
            for (int mt = 0; mt < 2; ++mt) {
                const int row = warp_m * 32 + mt * 16;
                a[mt][0] = As[(row + g)     * AS_S + ks + t];
                a[mt][1] = As[(row + g + 8) * AS_S + ks + t];
                a[mt][2] = As[(row + g)     * AS_S + ks + t + 4];
                a[mt][3] = As[(row + g + 8) * AS_S + ks + t + 4];
            }
            #pragma unroll
            for (int nt = 0; nt < 4; ++nt) {
                const int col = warp_n * 32 + nt * 8;
                b[nt][0] = Bs[(ks + t)     * BS_S + col + g];
                b[nt][1] = Bs[(ks + t + 4) * BS_S + col + g];
            }
            #pragma unroll
            for (int mt = 0; mt < 2; ++mt)
                #pragma unroll
                for (int nt = 0; nt < 4; ++nt)
                    asm volatile(
                        "mma.sync.aligned.m16n8k8.row.col.f32.tf32.tf32.f32 "
                        "{%0,%1,%2,%3}, {%4,%5,%6,%7}, {%8,%9}, {%0,%1,%2,%3};"
                        : "+f"(acc[mt][nt][0]), "+f"(acc[mt][nt][1]),
                          "+f"(acc[mt][nt][2]), "+f"(acc[mt][nt][3])
                        : "r"(a[mt][0]), "r"(a[mt][1]),
                          "r"(a[mt][2]), "r"(a[mt][3]),
                          "r"(b[nt][0]), "r"(b[nt][1]));
        }
        __syncthreads();
    }

    // epilogue: store eX = 2^(C2 * acc)
    #pragma unroll
    for (int mt = 0; mt < 2; ++mt) {
        #pragma unroll
        for (int nt = 0; nt < 4; ++nt) {
            const int row = rowbase + warp_m * 32 + mt * 16 + g;
            const int col = bn + warp_n * 32 + nt * 8 + 2 * t;
            *(float2*)&C[(size_t)row * 256 + col] =
                make_float2(ex2_fast(acc[mt][nt][0] * C2SCALE),
                            ex2_fast(acc[mt][nt][1] * C2SCALE));
            *(float2*)&C[(size_t)(row + 8) * 256 + col] =
                make_float2(ex2_fast(acc[mt][nt][2] * C2SCALE),
                            ex2_fast(acc[mt][nt][3] * C2SCALE));
        }
    }
}

// ----------------------------------------------------------------------------
// Partial-attention kernel. Grid: 512 = b*32 + qt*4 + ks. Block: 128 thr.
// Inner loop: x = fma2(eq, ek, 1); r = rcp2_nr(x); sc2 += w2*r  (all FMA pipe).
// score = wvsum - sum(2*w_v*r).
// ----------------------------------------------------------------------------
#define KB_STRIDE 36
#define KEYS_PB 128
#define KBUF_FLOATS (KEYS_PB * KB_STRIDE)
#define PA_SMEM_FLOATS (2 * KBUF_FLOATS + 8 * 256 + 256 + 8 * KEYS_PB + 32 + 8)
#define PA_SMEM_BYTES  (PA_SMEM_FLOATS * 4)

__global__ __launch_bounds__(128, 4)
void attn_partial_kernel(const float* __restrict__ values,
                         const int* __restrict__ valid_lens,
                         const float* __restrict__ w_v) {
    extern __shared__ float sm[];
    float* kbuf   = sm;                          // 2 x 128 x 36  (ek)
    float* qh_s   = kbuf + 2 * KBUF_FLOATS;      // 8 x 256       (eq)
    float* wv_s   = qh_s + 8 * 256;              // 256           (2*w_v)
    float* attn_s = wv_s + 256;                  // 8 x 128
    float* red1   = attn_s + 8 * KEYS_PB;        // 32
    float* fin_s  = red1 + 32;                   // 8

    const int tid   = threadIdx.x;
    const int bx    = blockIdx.x;
    const int b     = bx >> 5;
    const int qt    = (bx >> 2) & 7;
    const int ks    = bx & 3;
    const int kbase = ks * KEYS_PB;
    const int vlen  = valid_lens[b];

    if (kbase >= vlen) {
        if (tid < 8) {
            g_pm[bx * 8 + tid] = -1e30f;
            g_ps[bx * 8 + tid] = 0.0f;
        }
        return;
    }

    const int w    = tid >> 5;
    const int lane = tid & 31;
    const int key  = kbase + tid;
    const bool stage_ok  = key < vlen;
    const bool warp_live = (kbase + w * 32) < vlen;
    const int q0   = qt * 8;

    for (int i = tid; i < 512; i += 128)
        *(float4*)&qh_s[i * 4] =
            *(const float4*)&g_qh[((size_t)(b * 64 + q0)) * 256 + i * 4];
    if (tid < 64) {
        float4 wv4 = *(const float4*)&w_v[tid * 4];
        wv4.x *= 2.f; wv4.y *= 2.f; wv4.z *= 2.f; wv4.w *= 2.f;
        *(float4*)&wv_s[tid * 4] = wv4;
    }

    const float* khg = &g_kh[((size_t)b * 512 + key) * 256];
    #pragma unroll
    for (int pre = 0; pre < 2; ++pre) {
        if (stage_ok) {
            float* dst = &kbuf[pre * KBUF_FLOATS + tid * KB_STRIDE];
            const float* src = &khg[pre * 32];
            #pragma unroll
            for (int j = 0; j < 8; ++j)
                cp_async16(&dst[j * 4], &src[j * 4]);
        }
        cp_async_commit();
    }

    u64 sc2[8] = {0ULL, 0ULL, 0ULL, 0ULL, 0ULL, 0ULL, 0ULL, 0ULL};

    #pragma unroll 1
    for (int c = 0; c < 8; ++c) {
        if (c < 7) cp_async_wait1(); else cp_async_wait0();
        __syncthreads();

        if (warp_live) {
            const float* kb = &kbuf[(c & 1) * KBUF_FLOATS + tid * KB_STRIDE];
            const int hbase = c * 32;
            #pragma unroll 2
            for (int i = 0; i < 8; ++i) {
                // ek pair0/pair1 and w2 pair0/pair1 (shared across q)
                ulonglong2 ek = *(const ulonglong2*)&kb[i * 4];
                ulonglong2 w2 = *(const ulonglong2*)&wv_s[hbase + i * 4];
                #pragma unroll
                for (int q = 0; q < 8; ++q) {
                    ulonglong2 eq =
                        *(const ulonglong2*)&qh_s[q * 256 + hbase + i * 4];
                    u64 x0  = fma2(eq.x, ek.x, ONE2);
                    u64 x1  = fma2(eq.y, ek.y, ONE2);
                    u64 nx0 = fma2(eq.x, ek.x, ONE2 ^ 0x8000000080000000ULL);
                    (void)nx0;  // (see below: nx computed via mul)
                    u64 n0 = mul2(x0, 0xBF800000BF800000ULL);  // -x0
                    u64 n1 = mul2(x1, 0xBF800000BF800000ULL);  // -x1
                    u64 r0 = rcp2_nr(x0, n0);
                    u64 r1 = rcp2_nr(x1, n1);
                    sc2[q] = fma2(w2.x, r0, sc2[q]);
                    sc2[q] = fma2(w2.y, r1, sc2[q]);
                }
            }
        }

        __syncthreads();
        if (c < 6) {
            if (stage_ok) {
                float* dst = &kbuf[(c & 1) * KBUF_FLOATS + tid * KB_STRIDE];
                const float* src = &khg[(c + 2) * 32];
                #pragma unroll
                for (int j = 0; j < 8; ++j)
                    cp_async16(&dst[j * 4], &src[j * 4]);
            }
            cp_async_commit();
        }
    }

    // wvsum = sum_h w_v[h]  (wv_s holds 2*w_v)
    float wvsum = 0.f;
    #pragma unroll
    for (int i = 0; i < 8; ++i) wvsum += wv_s[lane + i * 32];
    #pragma unroll
    for (int o = 16; o; o >>= 1) wvsum += __shfl_xor_sync(0xffffffffu, wvsum, o);
    wvsum *= 0.5f;

    // ---- per-q score + max over this block's keys ----
    float sc[8];
    #pragma unroll
    for (int q = 0; q < 8; ++q) {
        float lo = __uint_as_float((unsigned)sc2[q]);
        float hi = __uint_as_float((unsigned)(sc2[q] >> 32));
        float v = wvsum - (lo + hi);          // score = sum w_v - sum 2 w_v r
        if (!stage_ok) v = -1e30f;
        sc[q] = v;
        #pragma unroll
        for (int o = 16; o; o >>= 1) v = fmaxf(v, __shfl_xor_sync(0xffffffffu, v, o));
        if (lane == 0) red1[q * 4 + w] = v;
    }
    __syncthreads();
    if (tid < 32) {
        float v = red1[tid];
        v = fmaxf(v, __shfl_xor_sync(0xffffffffu, v, 1));
        v = fmaxf(v, __shfl_xor_sync(0xffffffffu, v, 2));
        if ((tid & 3) == 0) {
            fin_s[tid >> 2] = v;
            g_pm[bx * 8 + (tid >> 2)] = v;
        }
    }
    __syncthreads();

    #pragma unroll
    for (int q = 0; q < 8; ++q) {
        float p = ex2_fast((sc[q] - fin_s[q]) * L2E);
        attn_s[q * KEYS_PB + tid] = p;
        float v = p;
        #pragma unroll
        for (int o = 16; o; o >>= 1) v += __shfl_xor_sync(0xffffffffu, v, o);
        if (lane == 0) red1[q * 4 + w] = v;
    }
    __syncthreads();
    if (tid < 32) {
        float v = red1[tid];
        v += __shfl_xor_sync(0xffffffffu, v, 1);
        v += __shfl_xor_sync(0xffffffffu, v, 2);
        if ((tid & 3) == 0) g_ps[bx * 8 + (tid >> 2)] = v;
    }
    __syncthreads();

    const int klim = min(KEYS_PB, vlen - kbase);
    const int v0 = tid * 2;
    const float* vp = values + ((size_t)b * 512 + kbase) * 256 + v0;
    float acc[8][2] = {};
    for (int k = 0; k < klim; ++k) {
        float2 vv = *(const float2*)&vp[(size_t)k * 256];
        #pragma unroll
        for (int q = 0; q < 8; ++q) {
            float a = attn_s[q * KEYS_PB + k];
            acc[q][0] = fmaf(a, vv.x, acc[q][0]);
            acc[q][1] = fmaf(a, vv.y, acc[q][1]);
        }
    }
    #pragma unroll
    for (int q = 0; q < 8; ++q)
        *(float2*)&g_po[((size_t)(bx * 8 + q)) * 256 + v0] =
            make_float2(acc[q][0], acc[q][1]);
}

// ----------------------------------------------------------------------------
// Combine kernel (unchanged).
// ----------------------------------------------------------------------------
__global__ __launch_bounds__(256)
void combine_kernel(float* __restrict__ out) {
    const int bx = blockIdx.x;
    const int b  = bx >> 3;
    const int qt = bx & 7;
    const int v  = threadIdx.x;
    const int pb = b * 32 + qt * 4;

    #pragma unroll
    for (int q = 0; q < 8; ++q) {
        float m0 = g_pm[(pb + 0) * 8 + q];
        float m1 = g_pm[(pb + 1) * 8 + q];
        float m2 = g_pm[(pb + 2) * 8 + q];
        float m3 = g_pm[(pb + 3) * 8 + q];
        float M = fmaxf(fmaxf(m0, m1), fmaxf(m2, m3));
        float w0 = ex2_fast((m0 - M) * L2E);
        float w1 = ex2_fast((m1 - M) * L2E);
        float w2 = ex2_fast((m2 - M) * L2E);
        float w3 = ex2_fast((m3 - M) * L2E);
        float den = w0 * g_ps[(pb + 0) * 8 + q] + w1 * g_ps[(pb + 1) * 8 + q]
                  + w2 * g_ps[(pb + 2) * 8 + q] + w3 * g_ps[(pb + 3) * 8 + q];
        float num = w0 * g_po[((size_t)((pb + 0) * 8 + q)) * 256 + v]
                  + w1 * g_po[((size_t)((pb + 1) * 8 + q)) * 256 + v]
                  + w2 * g_po[((size_t)((pb + 2) * 8 + q)) * 256 + v]
                  + w3 * g_po[((size_t)((pb + 3) * 8 + q)) * 256 + v];
        out[((size_t)(b * 64 + qt * 8 + q)) * 256 + v] = num * rcp_fast(den);
    }
}

// ----------------------------------------------------------------------------
extern "C" void kernel_launch(void* const* d_in, const int* in_sizes, int n_in,
                              void* d_out, int out_size) {
    (void)in_sizes; (void)n_in; (void)out_size;
    const float* queries = (const float*)d_in[0];   // [16,64,256]
    const float* keys    = (const float*)d_in[1];   // [16,512,256]
    const float* values  = (const float*)d_in[2];   // [16,512,256]
    const int*   vlens   = (const int*)  d_in[3];   // [16]
    const float* Wq      = (const float*)d_in[4];   // [256,256]
    const float* Wk      = (const float*)d_in[5];   // [256,256]
    const float* wv      = (const float*)d_in[6];   // [256]
    float* out = (float*)d_out;                     // [16,64,256]

    float *qh = nullptr, *kh = nullptr;
    cudaGetSymbolAddress((void**)&qh, g_qh);
    cudaGetSymbolAddress((void**)&kh, g_kh);

    cudaFuncSetAttribute(attn_partial_kernel,
                         cudaFuncAttributeMaxDynamicSharedMemorySize,
                         PA_SMEM_BYTES);

    proj_tf32_kernel<<<dim3(2, 144), 256>>>(queries, keys, Wq, Wk, vlens, qh, kh);
    attn_partial_kernel<<<512, 128, PA_SMEM_BYTES>>>(values, vlens, wv);
    combine_kernel<<<128, 256>>>(out);
}

// round 16
// speedup vs baseline: 1.0210x; 1.0210x over previous
#include <cuda_runtime.h>

// ============================================================================
// AdditiveAttention: out = softmax_k( sum_h w_v[h]*tanh(qW_q + kW_k) ) @ V
// B=16, NQ=64, NK=512, QS=KS=H=VD=256, fp32.
//
// R16 = R14 structure (tf32 proj + split-K partial + combine) with the score
// inner loop moved entirely onto the FMA/ALU pipes (scalar, 1:1 SASS mapping):
//   proj epilogue stores eq = 2^(C2*q), ek = 2^(C2*k)  (C2 = 2*log2 e)
//   per elem: x = fma(eq,ek,1); r = magic-seed; r *= fma(-x,r,2) x2 (Newton);
//             sc += (2*w_v)*r.      score = sum(w_v) - sum(2*w_v*r).
// 6 FFMA @ rt2 = 12 cyc/elem-warp vs TANH's measured ~29. R15's f32x2/u64
// version failed because ptxas split the packed ops; scalar avoids that.
// ============================================================================

// scratch (allocation-free rule -> __device__ globals; zero-initialized)
__device__ float g_qh[16 * 64 * 256];        // 4 MB: 2^(C2 * queries@W_q)
__device__ float g_kh[16 * 512 * 256];       // 8 MB: 2^(C2 * keys@W_k)
__device__ float g_po[512 * 8 * 256];        // 4 MB: partial outputs
__device__ float g_pm[512 * 8];              // partial maxes
__device__ float g_ps[512 * 8];              // partial sums

#define L2E     1.4426950408889634f
#define C2SCALE 2.885390081777927f           // 2*log2(e)

__device__ __forceinline__ float ex2_fast(float x) {
    float r; asm("ex2.approx.f32 %0, %1;" : "=f"(r) : "f"(x)); return r;
}
__device__ __forceinline__ float rcp_fast(float x) {
    float r; asm("rcp.approx.f32 %0, %1;" : "=f"(r) : "f"(x)); return r;
}
__device__ __forceinline__ unsigned f2tf32(float x) {
    unsigned u; asm("cvt.rna.tf32.f32 %0, %1;" : "=r"(u) : "f"(x)); return u;
}
// reciprocal of x >= 1: magic bit-seed + 2 Newton iterations, all FMA/ALU.
__device__ __forceinline__ float rcp_nr(float x) {
    float r = __uint_as_float(0x7EF311C3u - __float_as_uint(x));
    r = r * fmaf(-x, r, 2.0f);
    r = r * fmaf(-x, r, 2.0f);
    return r;
}
__device__ __forceinline__ void cp_async16(void* smem_dst, const void* gmem_src) {
    unsigned s = (unsigned)__cvta_generic_to_shared(smem_dst);
    asm volatile("cp.async.cg.shared.global [%0], [%1], 16;\n" :: "r"(s), "l"(gmem_src));
}
__device__ __forceinline__ void cp_async_commit() {
    asm volatile("cp.async.commit_group;\n" ::);
}
__device__ __forceinline__ void cp_async_wait1() {
    asm volatile("cp.async.wait_group 1;\n" ::);
}
__device__ __forceinline__ void cp_async_wait0() {
    asm volatile("cp.async.wait_group 0;\n" ::);
}

// ----------------------------------------------------------------------------
// tf32 tensor-core projection GEMM; epilogue stores 2^(C2*acc).
// BM=64, BN=128, BK=16, 256 thr (8 warps 2x4), warp tile 32x32.
// Grid (2,144) = 288 blocks, occ 2 -> one wave. Key blocks past vlen skipped.
// ----------------------------------------------------------------------------
#define AS_S 20
#define BS_S 140

__global__ __launch_bounds__(256, 2)
void proj_tf32_kernel(const float* __restrict__ queries,
                      const float* __restrict__ keys,
                      const float* __restrict__ Wq,
                      const float* __restrict__ Wk,
                      const int* __restrict__ valid_lens,
                      float* __restrict__ qh,
                      float* __restrict__ kh) {
    __shared__ unsigned As[64 * AS_S];
    __shared__ unsigned Bs[16 * BS_S];

    const int tid    = threadIdx.x;
    const int warp   = tid >> 5;
    const int lane   = tid & 31;
    const int g      = lane >> 2;
    const int t      = lane & 3;
    const int warp_m = warp & 1;
    const int warp_n = warp >> 1;
    const int bm     = blockIdx.y * 64;
    const int bn     = blockIdx.x * 128;

    const float* A; const float* W; float* C; int rowbase;
    if (bm < 1024) { A = queries; W = Wq; C = qh; rowbase = bm; }
    else {
        A = keys; W = Wk; C = kh; rowbase = bm - 1024;
        if ((rowbase & 511) >= valid_lens[rowbase >> 9]) return;
    }

    const int arow = tid >> 2;
    const int acol = (tid & 3) * 4;
    const int brow = tid >> 4;
    const int bcol = (tid & 15) * 4;

    float acc[2][4][4] = {};

    float4 av  = *(const float4*)&A[(rowbase + arow) * 256 + acol];
    float4 bv0 = *(const float4*)&W[brow * 256 + bn + bcol];
    float4 bv1 = *(const float4*)&W[brow * 256 + bn + bcol + 64];

    for (int k0 = 0; k0 < 256; k0 += 16) {
        {
            uint4 ua = make_uint4(f2tf32(av.x), f2tf32(av.y),
                                  f2tf32(av.z), f2tf32(av.w));
            *(uint4*)&As[arow * AS_S + acol] = ua;
            uint4 ub0 = make_uint4(f2tf32(bv0.x), f2tf32(bv0.y),
                                   f2tf32(bv0.z), f2tf32(bv0.w));
            uint4 ub1 = make_uint4(f2tf32(bv1.x), f2tf32(bv1.y),
                                   f2tf32(bv1.z), f2tf32(bv1.w));
            *(uint4*)&Bs[brow * BS_S + bcol]      = ub0;
            *(uint4*)&Bs[brow * BS_S + bcol + 64] = ub1;
        }
        __syncthreads();

        if (k0 + 16 < 256) {
            av  = *(const float4*)&A[(rowbase + arow) * 256 + k0 + 16 + acol];
            bv0 = *(const float4*)&W[(k0 + 16 + brow) * 256 + bn + bcol];
            bv1 = *(const float4*)&W[(k0 + 16 + brow) * 256 + bn + bcol + 64];
        }

        #pragma unroll
        for (int ks = 0; ks < 16; ks += 8) {
            unsigned a[2][4], b[4][2];
            #pragma unroll
            for (int mt = 0; mt < 2; ++mt) {
                const int row = warp_m * 32 + mt * 16;
                a[mt][0] = As[(row + g)     * AS_S + ks + t];
                a[mt][1] = As[(row + g + 8) * AS_S + ks + t];
                a[mt][2] = As[(row + g)     * AS_S + ks + t + 4];
                a[mt][3] = As[(row + g + 8) * AS_S + ks + t + 4];
            }
            #pragma unroll
            for (int nt = 0; nt < 4; ++nt) {
                const int col = warp_n * 32 + nt * 8;
                b[nt][0] = Bs[(ks + t)     * BS_S + col + g];
                b[nt][1] = Bs[(ks + t + 4) * BS_S + col + g];
            }
            #pragma unroll
            for (int mt = 0; mt < 2; ++mt)
                #pragma unroll
                for (int nt = 0; nt < 4; ++nt)
                    asm volatile(
                        "mma.sync.aligned.m16n8k8.row.col.f32.tf32.tf32.f32 "
                        "{%0,%1,%2,%3}, {%4,%5,%6,%7}, {%8,%9}, {%0,%1,%2,%3};"
                        : "+f"(acc[mt][nt][0]), "+f"(acc[mt][nt][1]),
                          "+f"(acc[mt][nt][2]), "+f"(acc[mt][nt][3])
                        : "r"(a[mt][0]), "r"(a[mt][1]),
                          "r"(a[mt][2]), "r"(a[mt][3]),
                          "r"(b[nt][0]), "r"(b[nt][1]));
        }
        __syncthreads();
    }

    // epilogue: store eX = 2^(C2 * acc)
    #pragma unroll
    for (int mt = 0; mt < 2; ++mt) {
        #pragma unroll
        for (int nt = 0; nt < 4; ++nt) {
            const int row = rowbase + warp_m * 32 + mt * 16 + g;
            const int col = bn + warp_n * 32 + nt * 8 + 2 * t;
            *(float2*)&C[(size_t)row * 256 + col] =
                make_float2(ex2_fast(acc[mt][nt][0] * C2SCALE),
                            ex2_fast(acc[mt][nt][1] * C2SCALE));
            *(float2*)&C[(size_t)(row + 8) * 256 + col] =
                make_float2(ex2_fast(acc[mt][nt][2] * C2SCALE),
                            ex2_fast(acc[mt][nt][3] * C2SCALE));
        }
    }
}

// ----------------------------------------------------------------------------
// Partial-attention kernel. Grid: 512 = b*32 + qt*4 + ks. Block: 128 thr.
// Score loop: all FMA/ALU pipe (Newton reciprocal), zero MUFU.
// ----------------------------------------------------------------------------
#define KB_STRIDE 36
#define KEYS_PB 128
#define KBUF_FLOATS (KEYS_PB * KB_STRIDE)
#define PA_SMEM_FLOATS (2 * KBUF_FLOATS + 8 * 256 + 256 + 8 * KEYS_PB + 32 + 8)
#define PA_SMEM_BYTES  (PA_SMEM_FLOATS * 4)

__global__ __launch_bounds__(128, 4)
void attn_partial_kernel(const float* __restrict__ values,
                         const int* __restrict__ valid_lens,
                         const float* __restrict__ w_v) {
    extern __shared__ float sm[];
    float* kbuf   = sm;                          // 2 x 128 x 36  (ek)
    float* qh_s   = kbuf + 2 * KBUF_FLOATS;      // 8 x 256       (eq)
    float* wv_s   = qh_s + 8 * 256;              // 256           (2*w_v)
    float* attn_s = wv_s + 256;                  // 8 x 128
    float* red1   = attn_s + 8 * KEYS_PB;        // 32
    float* fin_s  = red1 + 32;                   // 8

    const int tid   = threadIdx.x;
    const int bx    = blockIdx.x;
    const int b     = bx >> 5;
    const int qt    = (bx >> 2) & 7;
    const int ks    = bx & 3;
    const int kbase = ks * KEYS_PB;
    const int vlen  = valid_lens[b];

    if (kbase >= vlen) {
        if (tid < 8) {
            g_pm[bx * 8 + tid] = -1e30f;
            g_ps[bx * 8 + tid] = 0.0f;
        }
        return;
    }

    const int w    = tid >> 5;
    const int lane = tid & 31;
    const int key  = kbase + tid;
    const bool stage_ok  = key < vlen;
    const bool warp_live = (kbase + w * 32) < vlen;
    const int q0   = qt * 8;

    for (int i = tid; i < 512; i += 128)
        *(float4*)&qh_s[i * 4] =
            *(const float4*)&g_qh[((size_t)(b * 64 + q0)) * 256 + i * 4];
    if (tid < 64) {
        float4 wv4 = *(const float4*)&w_v[tid * 4];
        wv4.x *= 2.f; wv4.y *= 2.f; wv4.z *= 2.f; wv4.w *= 2.f;
        *(float4*)&wv_s[tid * 4] = wv4;
    }

    const float* khg = &g_kh[((size_t)b * 512 + key) * 256];
    #pragma unroll
    for (int pre = 0; pre < 2; ++pre) {
        if (stage_ok) {
            float* dst = &kbuf[pre * KBUF_FLOATS + tid * KB_STRIDE];
            const float* src = &khg[pre * 32];
            #pragma unroll
            for (int j = 0; j < 8; ++j)
                cp_async16(&dst[j * 4], &src[j * 4]);
        }
        cp_async_commit();
    }

    float sc[8] = {0.f, 0.f, 0.f, 0.f, 0.f, 0.f, 0.f, 0.f};

    #pragma unroll 1
    for (int c = 0; c < 8; ++c) {
        if (c < 7) cp_async_wait1(); else cp_async_wait0();
        __syncthreads();

        if (warp_live) {
            const float* kb = &kbuf[(c & 1) * KBUF_FLOATS + tid * KB_STRIDE];
            const int hbase = c * 32;
            #pragma unroll 2
            for (int i = 0; i < 8; ++i) {
                float4 kv = *(const float4*)&kb[i * 4];
                float4 w4 = *(const float4*)&wv_s[hbase + i * 4];
                #pragma unroll
                for (int q = 0; q < 8; ++q) {
                    float4 qv = *(const float4*)&qh_s[q * 256 + hbase + i * 4];
                    float x0 = fmaf(qv.x, kv.x, 1.0f);
                    float x1 = fmaf(qv.y, kv.y, 1.0f);
                    float x2 = fmaf(qv.z, kv.z, 1.0f);
                    float x3 = fmaf(qv.w, kv.w, 1.0f);
                    float r0 = rcp_nr(x0);
                    float r1 = rcp_nr(x1);
                    float r2 = rcp_nr(x2);
                    float r3 = rcp_nr(x3);
                    sc[q] = fmaf(w4.x, r0, sc[q]);
                    sc[q] = fmaf(w4.y, r1, sc[q]);
                    sc[q] = fmaf(w4.z, r2, sc[q]);
                    sc[q] = fmaf(w4.w, r3, sc[q]);
                }
            }
        }

        __syncthreads();
        if (c < 6) {
            if (stage_ok) {
                float* dst = &kbuf[(c & 1) * KBUF_FLOATS + tid * KB_STRIDE];
                const float* src = &khg[(c + 2) * 32];
                #pragma unroll
                for (int j = 0; j < 8; ++j)
                    cp_async16(&dst[j * 4], &src[j * 4]);
            }
            cp_async_commit();
        }
    }

    // wvsum = sum_h w_v[h]  (wv_s holds 2*w_v)
    float wvsum = 0.f;
    #pragma unroll
    for (int i = 0; i < 8; ++i) wvsum += wv_s[lane + i * 32];
    #pragma unroll
    for (int o = 16; o; o >>= 1) wvsum += __shfl_xor_sync(0xffffffffu, wvsum, o);
    wvsum *= 0.5f;

    // ---- per-q score + max over this block's keys ----
    #pragma unroll
    for (int q = 0; q < 8; ++q) {
        float v = wvsum - sc[q];              // score = sum w_v - sum 2 w_v r
        if (!stage_ok) v = -1e30f;
        sc[q] = v;
        #pragma unroll
        for (int o = 16; o; o >>= 1) v = fmaxf(v, __shfl_xor_sync(0xffffffffu, v, o));
        if (lane == 0) red1[q * 4 + w] = v;
    }
    __syncthreads();
    if (tid < 32) {
        float v = red1[tid];
        v = fmaxf(v, __shfl_xor_sync(0xffffffffu, v, 1));
        v = fmaxf(v, __shfl_xor_sync(0xffffffffu, v, 2));
        if ((tid & 3) == 0) {
            fin_s[tid >> 2] = v;
            g_pm[bx * 8 + (tid >> 2)] = v;
        }
    }
    __syncthreads();

    #pragma unroll
    for (int q = 0; q < 8; ++q) {
        float p = ex2_fast((sc[q] - fin_s[q]) * L2E);
        attn_s[q * KEYS_PB + tid] = p;
        float v = p;
        #pragma unroll
        for (int o = 16; o; o >>= 1) v += __shfl_xor_sync(0xffffffffu, v, o);
        if (lane == 0) red1[q * 4 + w] = v;
    }
    __syncthreads();
    if (tid < 32) {
        float v = red1[tid];
        v += __shfl_xor_sync(0xffffffffu, v, 1);
        v += __shfl_xor_sync(0xffffffffu, v, 2);
        if ((tid & 3) == 0) g_ps[bx * 8 + (tid >> 2)] = v;
    }
    __syncthreads();

    const int klim = min(KEYS_PB, vlen - kbase);
    const int v0 = tid * 2;
    const float* vp = values + ((size_t)b * 512 + kbase) * 256 + v0;
    float acc[8][2] = {};
    for (int k = 0; k < klim; ++k) {
        float2 vv = *(const float2*)&vp[(size_t)k * 256];
        #pragma unroll
        for (int q = 0; q < 8; ++q) {
            float a = attn_s[q * KEYS_PB + k];
            acc[q][0] = fmaf(a, vv.x, acc[q][0]);
            acc[q][1] = fmaf(a, vv.y, acc[q][1]);
        }
    }
    #pragma unroll
    for (int q = 0; q < 8; ++q)
        *(float2*)&g_po[((size_t)(bx * 8 + q)) * 256 + v0] =
            make_float2(acc[q][0], acc[q][1]);
}

// ----------------------------------------------------------------------------
// Combine kernel (unchanged).
// ----------------------------------------------------------------------------
__global__ __launch_bounds__(256)
void combine_kernel(float* __restrict__ out) {
    const int bx = blockIdx.x;
    const int b  = bx >> 3;
    const int qt = bx & 7;
    const int v  = threadIdx.x;
    const int pb = b * 32 + qt * 4;

    #pragma unroll
    for (int q = 0; q < 8; ++q) {
        float m0 = g_pm[(pb + 0) * 8 + q];
        float m1 = g_pm[(pb + 1) * 8 + q];
        float m2 = g_pm[(pb + 2) * 8 + q];
        float m3 = g_pm[(pb + 3) * 8 + q];
        float M = fmaxf(fmaxf(m0, m1), fmaxf(m2, m3));
        float w0 = ex2_fast((m0 - M) * L2E);
        float w1 = ex2_fast((m1 - M) * L2E);
        float w2 = ex2_fast((m2 - M) * L2E);
        float w3 = ex2_fast((m3 - M) * L2E);
        float den = w0 * g_ps[(pb + 0) * 8 + q] + w1 * g_ps[(pb + 1) * 8 + q]
                  + w2 * g_ps[(pb + 2) * 8 + q] + w3 * g_ps[(pb + 3) * 8 + q];
        float num = w0 * g_po[((size_t)((pb + 0) * 8 + q)) * 256 + v]
                  + w1 * g_po[((size_t)((pb + 1) * 8 + q)) * 256 + v]
                  + w2 * g_po[((size_t)((pb + 2) * 8 + q)) * 256 + v]
                  + w3 * g_po[((size_t)((pb + 3) * 8 + q)) * 256 + v];
        out[((size_t)(b * 64 + qt * 8 + q)) * 256 + v] = num * rcp_fast(den);
    }
}

// ----------------------------------------------------------------------------
extern "C" void kernel_launch(void* const* d_in, const int* in_sizes, int n_in,
                              void* d_out, int out_size) {
    (void)in_sizes; (void)n_in; (void)out_size;
    const float* queries = (const float*)d_in[0];   // [16,64,256]
    const float* keys    = (const float*)d_in[1];   // [16,512,256]
    const float* values  = (const float*)d_in[2];   // [16,512,256]
    const int*   vlens   = (const int*)  d_in[3];   // [16]
    const float* Wq      = (const float*)d_in[4];   // [256,256]
    const float* Wk      = (const float*)d_in[5];   // [256,256]
    const float* wv      = (const float*)d_in[6];   // [256]
    float* out = (float*)d_out;                     // [16,64,256]

    float *qh = nullptr, *kh = nullptr;
    cudaGetSymbolAddress((void**)&qh, g_qh);
    cudaGetSymbolAddress((void**)&kh, g_kh);

    cudaFuncSetAttribute(attn_partial_kernel,
                         cudaFuncAttributeMaxDynamicSharedMemorySize,
                         PA_SMEM_BYTES);

    proj_tf32_kernel<<<dim3(2, 144), 256>>>(queries, keys, Wq, Wk, vlens, qh, kh);
    attn_partial_kernel<<<512, 128, PA_SMEM_BYTES>>>(values, vlens, wv);
    combine_kernel<<<128, 256>>>(out);
}

// round 17
// speedup vs baseline: 1.0481x; 1.0265x over previous
#include <cuda_runtime.h>
#include <cuda_fp16.h>

// ============================================================================
// AdditiveAttention: out = softmax_k( sum_h w_v[h]*tanh(qW_q + kW_k) ) @ V
// B=16, NQ=64, NK=512, QS=KS=H=VD=256, fp32.
//
// R17 = R14 (best passing: tf32 proj + split-K partial + combine) with the
// score loop's MUFU count halved via tanh.approx.f16x2 (2 elems / MUFU op).
// Model (fits R11/R14/R16): MUFU is a per-SM shared unit on sm_103a —
// EX2/RCP ~4 cyc/warp-op-SM, TANH ~8. R14 partial is MUFU-bound at
// 15k warp-elems/SM * 8 = 120k cyc; halving MUFU ops -> ~60k cyc.
// x = q+k stays f32 (exact); pack->tanh2->unpack; accumulate f32.
// ============================================================================

// scratch (allocation-free rule -> __device__ globals; zero-initialized)
__device__ float g_qh[16 * 64 * 256];        // 4 MB: queries @ W_q
__device__ float g_kh[16 * 512 * 256];       // 8 MB: keys @ W_k
__device__ float g_po[512 * 8 * 256];        // 4 MB: partial outputs
__device__ float g_pm[512 * 8];              // partial maxes
__device__ float g_ps[512 * 8];              // partial sums

#define L2E 1.4426950408889634f

__device__ __forceinline__ float ex2_fast(float x) {
    float r; asm("ex2.approx.f32 %0, %1;" : "=f"(r) : "f"(x)); return r;
}
__device__ __forceinline__ float rcp_fast(float x) {
    float r; asm("rcp.approx.f32 %0, %1;" : "=f"(r) : "f"(x)); return r;
}
__device__ __forceinline__ unsigned f2tf32(float x) {
    unsigned u; asm("cvt.rna.tf32.f32 %0, %1;" : "=r"(u) : "f"(x)); return u;
}
// packed half2 tanh: ONE MUFU op for two elements
__device__ __forceinline__ __half2 tanh2(__half2 x) {
    unsigned xi = *(unsigned*)&x, ri;
    asm("tanh.approx.f16x2 %0, %1;" : "=r"(ri) : "r"(xi));
    return *(__half2*)&ri;
}
__device__ __forceinline__ void cp_async16(void* smem_dst, const void* gmem_src) {
    unsigned s = (unsigned)__cvta_generic_to_shared(smem_dst);
    asm volatile("cp.async.cg.shared.global [%0], [%1], 16;\n" :: "r"(s), "l"(gmem_src));
}
__device__ __forceinline__ void cp_async_commit() {
    asm volatile("cp.async.commit_group;\n" ::);
}
__device__ __forceinline__ void cp_async_wait1() {
    asm volatile("cp.async.wait_group 1;\n" ::);
}
__device__ __forceinline__ void cp_async_wait0() {
    asm volatile("cp.async.wait_group 0;\n" ::);
}

// ----------------------------------------------------------------------------
// tf32 tensor-core projection GEMM (R14, unchanged: stores raw projections).
// BM=64, BN=128, BK=16, 256 thr (8 warps 2x4), warp tile 32x32.
// Grid (2,144) = 288 blocks, occ 2 -> one wave. Key blocks past vlen skipped.
// ----------------------------------------------------------------------------
#define AS_S 20
#define BS_S 140

__global__ __launch_bounds__(256, 2)
void proj_tf32_kernel(const float* __restrict__ queries,
                      const float* __restrict__ keys,
                      const float* __restrict__ Wq,
                      const float* __restrict__ Wk,
                      const int* __restrict__ valid_lens,
                      float* __restrict__ qh,
                      float* __restrict__ kh) {
    __shared__ unsigned As[64 * AS_S];
    __shared__ unsigned Bs[16 * BS_S];

    const int tid    = threadIdx.x;
    const int warp   = tid >> 5;
    const int lane   = tid & 31;
    const int g      = lane >> 2;
    const int t      = lane & 3;
    const int warp_m = warp & 1;
    const int warp_n = warp >> 1;
    const int bm     = blockIdx.y * 64;
    const int bn     = blockIdx.x * 128;

    const float* A; const float* W; float* C; int rowbase;
    if (bm < 1024) { A = queries; W = Wq; C = qh; rowbase = bm; }
    else {
        A = keys; W = Wk; C = kh; rowbase = bm - 1024;
        if ((rowbase & 511) >= valid_lens[rowbase >> 9]) return;
    }

    const int arow = tid >> 2;
    const int acol = (tid & 3) * 4;
    const int brow = tid >> 4;
    const int bcol = (tid & 15) * 4;

    float acc[2][4][4] = {};

    float4 av  = *(const float4*)&A[(rowbase + arow) * 256 + acol];
    float4 bv0 = *(const float4*)&W[brow * 256 + bn + bcol];
    float4 bv1 = *(const float4*)&W[brow * 256 + bn + bcol + 64];

    for (int k0 = 0; k0 < 256; k0 += 16) {
        {
            uint4 ua = make_uint4(f2tf32(av.x), f2tf32(av.y),
                                  f2tf32(av.z), f2tf32(av.w));
            *(uint4*)&As[arow * AS_S + acol] = ua;
            uint4 ub0 = make_uint4(f2tf32(bv0.x), f2tf32(bv0.y),
                                   f2tf32(bv0.z), f2tf32(bv0.w));
            uint4 ub1 = make_uint4(f2tf32(bv1.x), f2tf32(bv1.y),
                                   f2tf32(bv1.z), f2tf32(bv1.w));
            *(uint4*)&Bs[brow * BS_S + bcol]      = ub0;
            *(uint4*)&Bs[brow * BS_S + bcol + 64] = ub1;
        }
        __syncthreads();

        if (k0 + 16 < 256) {
            av  = *(const float4*)&A[(rowbase + arow) * 256 + k0 + 16 + acol];
            bv0 = *(const float4*)&W[(k0 + 16 + brow) * 256 + bn + bcol];
            bv1 = *(const float4*)&W[(k0 + 16 + brow) * 256 + bn + bcol + 64];
        }

        #pragma unroll
        for (int ks = 0; ks < 16; ks += 8) {
            unsigned a[2][4], b[4][2];
            #pragma unroll
            for (int mt = 0; mt < 2; ++mt) {
                const int row = warp_m * 32 + mt * 16;
                a[mt][0] = As[(row + g)     * AS_S + ks + t];
                a[mt][1] = As[(row + g + 8) * AS_S + ks + t];
                a[mt][2] = As[(row + g)     * AS_S + ks + t + 4];
                a[mt][3] = As[(row + g + 8) * AS_S + ks + t + 4];
            }
            #pragma unroll
            for (int nt = 0; nt < 4; ++nt) {
                const int col = warp_n * 32 + nt * 8;
                b[nt][0] = Bs[(ks + t)     * BS_S + col + g];
                b[nt][1] = Bs[(ks + t + 4) * BS_S + col + g];
            }
            #pragma unroll
            for (int mt = 0; mt < 2; ++mt)
                #pragma unroll
                for (int nt = 0; nt < 4; ++nt)
                    asm volatile(
                        "mma.sync.aligned.m16n8k8.row.col.f32.tf32.tf32.f32 "
                        "{%0,%1,%2,%3}, {%4,%5,%6,%7}, {%8,%9}, {%0,%1,%2,%3};"
                        : "+f"(acc[mt][nt][0]), "+f"(acc[mt][nt][1]),
                          "+f"(acc[mt][nt][2]), "+f"(acc[mt][nt][3])
                        : "r"(a[mt][0]), "r"(a[mt][1]),
                          "r"(a[mt][2]), "r"(a[mt][3]),
                          "r"(b[nt][0]), "r"(b[nt][1]));
        }
        __syncthreads();
    }

    #pragma unroll
    for (int mt = 0; mt < 2; ++mt) {
        #pragma unroll
        for (int nt = 0; nt < 4; ++nt) {
            const int row = rowbase + warp_m * 32 + mt * 16 + g;
            const int col = bn + warp_n * 32 + nt * 8 + 2 * t;
            *(float2*)&C[(size_t)row * 256 + col] =
                make_float2(acc[mt][nt][0], acc[mt][nt][1]);
            *(float2*)&C[(size_t)(row + 8) * 256 + col] =
                make_float2(acc[mt][nt][2], acc[mt][nt][3]);
        }
    }
}

// ----------------------------------------------------------------------------
// Partial-attention kernel. Grid: 512 = b*32 + qt*4 + ks. Block: 128 thr.
// Score loop: f32 add -> f16x2 pack -> tanh.approx.f16x2 (0.5 MUFU/elem)
// -> f32 unpack -> f32 FFMA accumulate.
// ----------------------------------------------------------------------------
#define KB_STRIDE 36
#define KEYS_PB 128
#define KBUF_FLOATS (KEYS_PB * KB_STRIDE)
#define PA_SMEM_FLOATS (2 * KBUF_FLOATS + 8 * 256 + 256 + 8 * KEYS_PB + 32 + 8)
#define PA_SMEM_BYTES  (PA_SMEM_FLOATS * 4)

__global__ __launch_bounds__(128, 4)
void attn_partial_kernel(const float* __restrict__ values,
                         const int* __restrict__ valid_lens,
                         const float* __restrict__ w_v) {
    extern __shared__ float sm[];
    float* kbuf   = sm;                          // 2 x 128 x 36
    float* qh_s   = kbuf + 2 * KBUF_FLOATS;      // 8 x 256
    float* wv_s   = qh_s + 8 * 256;              // 256
    float* attn_s = wv_s + 256;                  // 8 x 128
    float* red1   = attn_s + 8 * KEYS_PB;        // 32
    float* fin_s  = red1 + 32;                   // 8

    const int tid   = threadIdx.x;
    const int bx    = blockIdx.x;
    const int b     = bx >> 5;
    const int qt    = (bx >> 2) & 7;
    const int ks    = bx & 3;
    const int kbase = ks * KEYS_PB;
    const int vlen  = valid_lens[b];

    if (kbase >= vlen) {
        if (tid < 8) {
            g_pm[bx * 8 + tid] = -1e30f;
            g_ps[bx * 8 + tid] = 0.0f;
        }
        return;
    }

    const int w    = tid >> 5;
    const int lane = tid & 31;
    const int key  = kbase + tid;
    const bool stage_ok  = key < vlen;
    const bool warp_live = (kbase + w * 32) < vlen;
    const int q0   = qt * 8;

    for (int i = tid; i < 512; i += 128)
        *(float4*)&qh_s[i * 4] =
            *(const float4*)&g_qh[((size_t)(b * 64 + q0)) * 256 + i * 4];
    if (tid < 64)
        *(float4*)&wv_s[tid * 4] = *(const float4*)&w_v[tid * 4];

    const float* khg = &g_kh[((size_t)b * 512 + key) * 256];
    #pragma unroll
    for (int pre = 0; pre < 2; ++pre) {
        if (stage_ok) {
            float* dst = &kbuf[pre * KBUF_FLOATS + tid * KB_STRIDE];
            const float* src = &khg[pre * 32];
            #pragma unroll
            for (int j = 0; j < 8; ++j)
                cp_async16(&dst[j * 4], &src[j * 4]);
        }
        cp_async_commit();
    }

    float sc[8] = {0.f, 0.f, 0.f, 0.f, 0.f, 0.f, 0.f, 0.f};

    #pragma unroll 1
    for (int c = 0; c < 8; ++c) {
        if (c < 7) cp_async_wait1(); else cp_async_wait0();
        __syncthreads();

        if (warp_live) {
            const float* kb = &kbuf[(c & 1) * KBUF_FLOATS + tid * KB_STRIDE];
            const int hbase = c * 32;
            #pragma unroll 2
            for (int i = 0; i < 8; ++i) {
                float4 kv = *(const float4*)&kb[i * 4];
                float4 w4 = *(const float4*)&wv_s[hbase + i * 4];
                #pragma unroll
                for (int q = 0; q < 8; ++q) {
                    float4 qv = *(const float4*)&qh_s[q * 256 + hbase + i * 4];
                    // exact f32 adds, then packed f16x2 tanh (2 elems / MUFU)
                    __half2 h01 = __floats2half2_rn(qv.x + kv.x, qv.y + kv.y);
                    __half2 h23 = __floats2half2_rn(qv.z + kv.z, qv.w + kv.w);
                    float2 t01 = __half22float2(tanh2(h01));
                    float2 t23 = __half22float2(tanh2(h23));
                    sc[q] = fmaf(w4.x, t01.x, sc[q]);
                    sc[q] = fmaf(w4.y, t01.y, sc[q]);
                    sc[q] = fmaf(w4.z, t23.x, sc[q]);
                    sc[q] = fmaf(w4.w, t23.y, sc[q]);
                }
            }
        }

        __syncthreads();
        if (c < 6) {
            if (stage_ok) {
                float* dst = &kbuf[(c & 1) * KBUF_FLOATS + tid * KB_STRIDE];
                const float* src = &khg[(c + 2) * 32];
                #pragma unroll
                for (int j = 0; j < 8; ++j)
                    cp_async16(&dst[j * 4], &src[j * 4]);
            }
            cp_async_commit();
        }
    }

    // ---- per-q score + max over this block's keys ----
    #pragma unroll
    for (int q = 0; q < 8; ++q) {
        float v = sc[q];
        if (!stage_ok) v = -1e30f;
        sc[q] = v;
        #pragma unroll
        for (int o = 16; o; o >>= 1) v = fmaxf(v, __shfl_xor_sync(0xffffffffu, v, o));
        if (lane == 0) red1[q * 4 + w] = v;
    }
    __syncthreads();
    if (tid < 32) {
        float v = red1[tid];
        v = fmaxf(v, __shfl_xor_sync(0xffffffffu, v, 1));
        v = fmaxf(v, __shfl_xor_sync(0xffffffffu, v, 2));
        if ((tid & 3) == 0) {
            fin_s[tid >> 2] = v;
            g_pm[bx * 8 + (tid >> 2)] = v;
        }
    }
    __syncthreads();

    #pragma unroll
    for (int q = 0; q < 8; ++q) {
        float p = ex2_fast((sc[q] - fin_s[q]) * L2E);
        attn_s[q * KEYS_PB + tid] = p;
        float v = p;
        #pragma unroll
        for (int o = 16; o; o >>= 1) v += __shfl_xor_sync(0xffffffffu, v, o);
        if (lane == 0) red1[q * 4 + w] = v;
    }
    __syncthreads();
    if (tid < 32) {
        float v = red1[tid];
        v += __shfl_xor_sync(0xffffffffu, v, 1);
        v += __shfl_xor_sync(0xffffffffu, v, 2);
        if ((tid & 3) == 0) g_ps[bx * 8 + (tid >> 2)] = v;
    }
    __syncthreads();

    const int klim = min(KEYS_PB, vlen - kbase);
    const int v0 = tid * 2;
    const float* vp = values + ((size_t)b * 512 + kbase) * 256 + v0;
    float acc[8][2] = {};
    for (int k = 0; k < klim; ++k) {
        float2 vv = *(const float2*)&vp[(size_t)k * 256];
        #pragma unroll
        for (int q = 0; q < 8; ++q) {
            float a = attn_s[q * KEYS_PB + k];
            acc[q][0] = fmaf(a, vv.x, acc[q][0]);
            acc[q][1] = fmaf(a, vv.y, acc[q][1]);
        }
    }
    #pragma unroll
    for (int q = 0; q < 8; ++q)
        *(float2*)&g_po[((size_t)(bx * 8 + q)) * 256 + v0] =
            make_float2(acc[q][0], acc[q][1]);
}

// ----------------------------------------------------------------------------
// Combine kernel (unchanged).
// ----------------------------------------------------------------------------
__global__ __launch_bounds__(256)
void combine_kernel(float* __restrict__ out) {
    const int bx = blockIdx.x;
    const int b  = bx >> 3;
    const int qt = bx & 7;
    const int v  = threadIdx.x;
    const int pb = b * 32 + qt * 4;

    #pragma unroll
    for (int q = 0; q < 8; ++q) {
        float m0 = g_pm[(pb + 0) * 8 + q];
        float m1 = g_pm[(pb + 1) * 8 + q];
        float m2 = g_pm[(pb + 2) * 8 + q];
        float m3 = g_pm[(pb + 3) * 8 + q];
        float M = fmaxf(fmaxf(m0, m1), fmaxf(m2, m3));
        float w0 = ex2_fast((m0 - M) * L2E);
        float w1 = ex2_fast((m1 - M) * L2E);
        float w2 = ex2_fast((m2 - M) * L2E);
        float w3 = ex2_fast((m3 - M) * L2E);
        float den = w0 * g_ps[(pb + 0) * 8 + q] + w1 * g_ps[(pb + 1) * 8 + q]
                  + w2 * g_ps[(pb + 2) * 8 + q] + w3 * g_ps[(pb + 3) * 8 + q];
        float num = w0 * g_po[((size_t)((pb + 0) * 8 + q)) * 256 + v]
                  + w1 * g_po[((size_t)((pb + 1) * 8 + q)) * 256 + v]
                  + w2 * g_po[((size_t)((pb + 2) * 8 + q)) * 256 + v]
                  + w3 * g_po[((size_t)((pb + 3) * 8 + q)) * 256 + v];
        out[((size_t)(b * 64 + qt * 8 + q)) * 256 + v] = num * rcp_fast(den);
    }
}

// ----------------------------------------------------------------------------
extern "C" void kernel_launch(void* const* d_in, const int* in_sizes, int n_in,
                              void* d_out, int out_size) {
    (void)in_sizes; (void)n_in; (void)out_size;
    const float* queries = (const float*)d_in[0];   // [16,64,256]
    const float* keys    = (const float*)d_in[1];   // [16,512,256]
    const float* values  = (const float*)d_in[2];   // [16,512,256]
    const int*   vlens   = (const int*)  d_in[3];   // [16]
    const float* Wq      = (const float*)d_in[4];   // [256,256]
    const float* Wk      = (const float*)d_in[5];   // [256,256]
    const float* wv      = (const float*)d_in[6];   // [256]
    float* out = (float*)d_out;                     // [16,64,256]

    float *qh = nullptr, *kh = nullptr;
    cudaGetSymbolAddress((void**)&qh, g_qh);
    cudaGetSymbolAddress((void**)&kh, g_kh);

    cudaFuncSetAttribute(attn_partial_kernel,
                         cudaFuncAttributeMaxDynamicSharedMemorySize,
                         PA_SMEM_BYTES);

    proj_tf32_kernel<<<dim3(2, 144), 256>>>(queries, keys, Wq, Wk, vlens, qh, kh);
    attn_partial_kernel<<<512, 128, PA_SMEM_BYTES>>>(values, vlens, wv);
    combine_kernel<<<128, 256>>>(out);
}